// round 4
// baseline (speedup 1.0000x reference)
#include <cuda_runtime.h>
#include <math.h>

#define B   16
#define T   12
#define NN  8600
#define H   64
#define E2  128
#define KK  66
#define ROWS_TILE 32
#define NODES_PER_CTA 128
#define CHUNKS ((NN + NODES_PER_CTA - 1) / NODES_PER_CTA)   // 68
#define OUT_LAST_OFF ((size_t)B * T * NN * H)               // 105,676,800

// ---------------- scratch (device globals: no allocations allowed) -------------
__device__ __align__(16) float g_agg_gate[B * E2];
__device__ __align__(16) float g_agg_upd[B * H];
__device__ __align__(128) float g_r[(size_t)B * NN * H];     // gate r     (35.2 MB)
__device__ __align__(128) float g_resu[(size_t)B * NN * H];  // res_upd    (35.2 MB)

// ---------------- f32x2 helpers (packed dual-FMA, Blackwell FFMA2) -------------
__device__ __forceinline__ unsigned long long pack2(float a) {
    unsigned long long r;
    unsigned int u = __float_as_uint(a);
    asm("mov.b64 %0, {%1, %1};" : "=l"(r) : "r"(u));
    return r;
}
__device__ __forceinline__ void fma2(unsigned long long& d, unsigned long long a,
                                     unsigned long long b) {
    asm("fma.rn.f32x2 %0, %1, %2, %3;" : "=l"(d) : "l"(a), "l"(b), "l"(d));
}
__device__ __forceinline__ void unpack2(unsigned long long v, float& x, float& y) {
    asm("mov.b64 {%0, %1}, %2;" : "=f"(x), "=f"(y) : "l"(v));
}

__device__ __forceinline__ float sigmoidf_(float x) {
    return 1.0f / (1.0f + __expf(-x));
}

// =========================== K0: zero the agg buffers ==========================
__global__ void k_zero() {
    int i = blockIdx.x * blockDim.x + threadIdx.x;
    if (i < B * E2) g_agg_gate[i] = 0.0f;
    if (i < B * H)  g_agg_upd[i] = 0.0f;
}

// ============ K1: h_gate = relu([x,state] @ gate_w + b), agg over nodes ========
__global__ void __launch_bounds__(256) k_gate_agg(
    const float* __restrict__ x, const float* __restrict__ state, int sbstride,
    const float* __restrict__ Wg, const float* __restrict__ bg, int t)
{
    __shared__ float sW[KK * E2];         // 66 x 128
    __shared__ float sb[E2];
    __shared__ float sin_[ROWS_TILE * 67];

    int tid = threadIdx.x;
    int b = blockIdx.y;
    int node_base = blockIdx.x * NODES_PER_CTA;

    for (int i = tid; i < KK * E2; i += 256) sW[i] = Wg[i];
    if (tid < E2) sb[tid] = bg[tid];

    int rl = tid & 31;        // row-lane within tile (warp covers 32 rows)
    int eg = tid >> 5;        // column group: 8 groups x 16 cols
    int e0 = eg * 16;

    float colsum[16];
#pragma unroll
    for (int j = 0; j < 16; j++) colsum[j] = 0.0f;

    const float* xb  = x + ((size_t)(b * T + t) * NN) * 2;
    const float* stb = state + (size_t)b * sbstride;

    for (int tile = 0; tile < NODES_PER_CTA / ROWS_TILE; tile++) {
        int n0 = node_base + tile * ROWS_TILE;
        __syncthreads();
        for (int i = tid; i < ROWS_TILE * KK; i += 256) {
            int r = i / KK, k = i - r * KK;
            int n = n0 + r;
            float v = 0.0f;
            if (n < NN) v = (k < 2) ? xb[(size_t)n * 2 + k]
                                    : stb[(size_t)n * H + (k - 2)];
            sin_[r * 67 + k] = v;
        }
        __syncthreads();

        int n = n0 + rl;
        unsigned long long acc[8];
#pragma unroll
        for (int j = 0; j < 8; j++) acc[j] = 0ULL;

        const float* srow = &sin_[rl * 67];
#pragma unroll 11
        for (int k = 0; k < KK; k++) {
            unsigned long long a2 = pack2(srow[k]);
            const ulonglong2* w2 = (const ulonglong2*)&sW[k * E2 + e0];
            ulonglong2 p0 = w2[0], p1 = w2[1], p2 = w2[2], p3 = w2[3];
            fma2(acc[0], a2, p0.x); fma2(acc[1], a2, p0.y);
            fma2(acc[2], a2, p1.x); fma2(acc[3], a2, p1.y);
            fma2(acc[4], a2, p2.x); fma2(acc[5], a2, p2.y);
            fma2(acc[6], a2, p3.x); fma2(acc[7], a2, p3.y);
        }
        if (n < NN) {
#pragma unroll
            for (int j = 0; j < 8; j++) {
                float v0, v1; unpack2(acc[j], v0, v1);
                v0 += sb[e0 + 2 * j];
                v1 += sb[e0 + 2 * j + 1];
                colsum[2 * j]     += fmaxf(v0, 0.0f);
                colsum[2 * j + 1] += fmaxf(v1, 0.0f);
            }
        }
    }

    // warp reduce across the 32 row-lanes, one atomicAdd per column per CTA
#pragma unroll
    for (int j = 0; j < 16; j++) {
        float v = colsum[j];
#pragma unroll
        for (int o = 16; o > 0; o >>= 1) v += __shfl_xor_sync(0xffffffffu, v, o);
        colsum[j] = v;
    }
    if (rl == 0) {
#pragma unroll
        for (int j = 0; j < 16; j++)
            atomicAdd(&g_agg_gate[b * E2 + e0 + j], colsum[j]);
    }
}

// ===== K2: res_gate -> sigmoid(zr); cand matmuls; store r, res_upd; agg_upd ====
extern __shared__ float sdyn[];
__global__ void __launch_bounds__(256) k_mid(
    const float* __restrict__ x, const float* __restrict__ state, int sbstride,
    const float* __restrict__ Wga, const float* __restrict__ bga,
    const float* __restrict__ Wuw, const float* __restrict__ buw,
    const float* __restrict__ Wua, const float* __restrict__ bua,
    const float* __restrict__ affw, const float* __restrict__ affb,
    const float* __restrict__ nodew, const float* __restrict__ addw, int t)
{
    float* sWa  = sdyn;                 // gate_align_w  66x128
    float* sWu  = sWa + KK * E2;        // [upd_w | upd_align_w]  66x128
    float* sba  = sWu + KK * E2;        // 128
    float* sbu  = sba + E2;             // [upd_b | upd_align_b]  128
    float* sin_ = sbu + E2;             // 32 x 67

    int tid = threadIdx.x;
    int b = blockIdx.y;
    int node_base = blockIdx.x * NODES_PER_CTA;

    for (int i = tid; i < KK * E2; i += 256) {
        sWa[i] = Wga[i];
        int k = i >> 7, e = i & 127;
        sWu[i] = (e < H) ? Wuw[k * H + e] : Wua[k * H + (e - H)];
    }
    if (tid < E2) {
        sba[tid] = bga[tid];
        sbu[tid] = (tid < H) ? buw[tid] : bua[tid - H];
    }

    int rl = tid & 31;
    int eg = tid >> 5;
    int e0 = eg * 16;

    float aggv[16];
#pragma unroll
    for (int j = 0; j < 16; j++) aggv[j] = g_agg_gate[b * E2 + e0 + j];

    float colsum[16];
#pragma unroll
    for (int j = 0; j < 16; j++) colsum[j] = 0.0f;

    const float* xb  = x + ((size_t)(b * T + t) * NN) * 2;
    const float* stb = state + (size_t)b * sbstride;

    for (int tile = 0; tile < NODES_PER_CTA / ROWS_TILE; tile++) {
        int n0 = node_base + tile * ROWS_TILE;
        __syncthreads();   // previous tile's upd reads done; weight load done
        for (int i = tid; i < ROWS_TILE * KK; i += 256) {
            int r = i / KK, k = i - r * KK;
            int n = n0 + r;
            float v = 0.0f;
            if (n < NN) v = (k < 2) ? xb[(size_t)n * 2 + k]
                                    : stb[(size_t)n * H + (k - 2)];
            sin_[r * 67 + k] = v;
        }
        __syncthreads();

        int n = n0 + rl;
        bool valid = (n < NN);
        const float* srow = &sin_[rl * 67];

        // ---- gate align dot: res[16] ----
        unsigned long long acc[8];
#pragma unroll
        for (int j = 0; j < 8; j++) acc[j] = 0ULL;
#pragma unroll 11
        for (int k = 0; k < KK; k++) {
            unsigned long long a2 = pack2(srow[k]);
            const ulonglong2* w2 = (const ulonglong2*)&sWa[k * E2 + e0];
            ulonglong2 p0 = w2[0], p1 = w2[1], p2 = w2[2], p3 = w2[3];
            fma2(acc[0], a2, p0.x); fma2(acc[1], a2, p0.y);
            fma2(acc[2], a2, p1.x); fma2(acc[3], a2, p1.y);
            fma2(acc[4], a2, p2.x); fma2(acc[5], a2, p2.y);
            fma2(acc[6], a2, p3.x); fma2(acc[7], a2, p3.y);
        }

        float zr[16];
        {
            float sgn = 0.0f;
            float aw[16], ab[16];
            if (valid) {
                sgn = addw[n] * nodew[n];
                const float4* awp = (const float4*)&affw[(size_t)n * E2 + e0];
                const float4* abp = (const float4*)&affb[(size_t)n * E2 + e0];
#pragma unroll
                for (int q = 0; q < 4; q++) {
                    ((float4*)aw)[q] = awp[q];
                    ((float4*)ab)[q] = abp[q];
                }
            }
#pragma unroll
            for (int j = 0; j < 8; j++) {
                float v0, v1; unpack2(acc[j], v0, v1);
                float p0 = v0 + sba[e0 + 2 * j];
                float p1 = v1 + sba[e0 + 2 * j + 1];
                if (valid) {
                    p0 += aw[2 * j] * sgn * aggv[2 * j] + ab[2 * j];
                    p1 += aw[2 * j + 1] * sgn * aggv[2 * j + 1] + ab[2 * j + 1];
                }
                zr[2 * j]     = sigmoidf_(p0);
                zr[2 * j + 1] = sigmoidf_(p1);
            }
        }

        __syncthreads();  // everyone done reading sin_ state part
        if (eg < 4) {
            // z part (cols 0..63): cand state = z * state, in place
#pragma unroll
            for (int j = 0; j < 16; j++)
                sin_[rl * 67 + 2 + e0 + j] *= zr[j];
        } else if (valid) {
            // r part (cols 64..127): store
            float* rp = &g_r[((size_t)b * NN + n) * H + (e0 - 64)];
            ((float4*)rp)[0] = make_float4(zr[0], zr[1], zr[2], zr[3]);
            ((float4*)rp)[1] = make_float4(zr[4], zr[5], zr[6], zr[7]);
            ((float4*)rp)[2] = make_float4(zr[8], zr[9], zr[10], zr[11]);
            ((float4*)rp)[3] = make_float4(zr[12], zr[13], zr[14], zr[15]);
        }
        __syncthreads();

        // ---- update dot: cols 0..63 = upd_w (relu+agg), 64..127 = upd_align ---
#pragma unroll
        for (int j = 0; j < 8; j++) acc[j] = 0ULL;
#pragma unroll 11
        for (int k = 0; k < KK; k++) {
            unsigned long long a2 = pack2(srow[k]);
            const ulonglong2* w2 = (const ulonglong2*)&sWu[k * E2 + e0];
            ulonglong2 p0 = w2[0], p1 = w2[1], p2 = w2[2], p3 = w2[3];
            fma2(acc[0], a2, p0.x); fma2(acc[1], a2, p0.y);
            fma2(acc[2], a2, p1.x); fma2(acc[3], a2, p1.y);
            fma2(acc[4], a2, p2.x); fma2(acc[5], a2, p2.y);
            fma2(acc[6], a2, p3.x); fma2(acc[7], a2, p3.y);
        }
        if (eg < 4) {
            if (valid) {
#pragma unroll
                for (int j = 0; j < 8; j++) {
                    float v0, v1; unpack2(acc[j], v0, v1);
                    colsum[2 * j]     += fmaxf(v0 + sbu[e0 + 2 * j], 0.0f);
                    colsum[2 * j + 1] += fmaxf(v1 + sbu[e0 + 2 * j + 1], 0.0f);
                }
            }
        } else if (valid) {
            float ru[16];
#pragma unroll
            for (int j = 0; j < 8; j++) {
                float v0, v1; unpack2(acc[j], v0, v1);
                ru[2 * j]     = v0 + sbu[e0 + 2 * j];
                ru[2 * j + 1] = v1 + sbu[e0 + 2 * j + 1];
            }
            float* rp = &g_resu[((size_t)b * NN + n) * H + (e0 - 64)];
            ((float4*)rp)[0] = make_float4(ru[0], ru[1], ru[2], ru[3]);
            ((float4*)rp)[1] = make_float4(ru[4], ru[5], ru[6], ru[7]);
            ((float4*)rp)[2] = make_float4(ru[8], ru[9], ru[10], ru[11]);
            ((float4*)rp)[3] = make_float4(ru[12], ru[13], ru[14], ru[15]);
        }
    }

    if (eg < 4) {  // warp-uniform branch
#pragma unroll
        for (int j = 0; j < 16; j++) {
            float v = colsum[j];
#pragma unroll
            for (int o = 16; o > 0; o >>= 1) v += __shfl_xor_sync(0xffffffffu, v, o);
            colsum[j] = v;
        }
        if (rl == 0) {
#pragma unroll
            for (int j = 0; j < 16; j++)
                atomicAdd(&g_agg_upd[b * H + e0 + j], colsum[j]);
        }
    }
}

// ========= K3: hc = tanh(res_upd + aff*s*agg + affb); h = r*s + (1-r)*hc ========
__global__ void __launch_bounds__(256) k_final(
    const float* __restrict__ state, int sbstride,
    const float* __restrict__ affw, const float* __restrict__ affb,
    const float* __restrict__ nodew, const float* __restrict__ addw,
    float* __restrict__ out, int t)
{
    int tid = threadIdx.x;
    int row = blockIdx.x * 16 + (tid >> 4);     // 16 rows / block
    if (row >= B * NN) return;
    int b = row / NN, n = row - b * NN;
    int q = (tid & 15) * 4;

    size_t ro = (size_t)row * H + q;
    float4 r4  = *(const float4*)&g_r[ro];
    float4 ru4 = *(const float4*)&g_resu[ro];
    float4 st4 = *(const float4*)(state + (size_t)b * sbstride + (size_t)n * H + q);
    float  su  = addw[n] * nodew[n];
    float4 aw4 = *(const float4*)&affw[(size_t)n * H + q];
    float4 ab4 = *(const float4*)&affb[(size_t)n * H + q];
    float4 ag4 = *(const float4*)&g_agg_upd[b * H + q];

    float4 o;
    o.x = r4.x * st4.x + (1.0f - r4.x) * tanhf(ru4.x + aw4.x * su * ag4.x + ab4.x);
    o.y = r4.y * st4.y + (1.0f - r4.y) * tanhf(ru4.y + aw4.y * su * ag4.y + ab4.y);
    o.z = r4.z * st4.z + (1.0f - r4.z) * tanhf(ru4.z + aw4.z * su * ag4.z + ab4.z);
    o.w = r4.w * st4.w + (1.0f - r4.w) * tanhf(ru4.w + aw4.w * su * ag4.w + ab4.w);

    *(float4*)(out + ((size_t)(b * T + t) * NN + n) * H + q) = o;
    if (t == T - 1)
        *(float4*)(out + OUT_LAST_OFF + ((size_t)b * NN + n) * H + q) = o;
}

// =============================== launch ========================================
extern "C" void kernel_launch(void* const* d_in, const int* in_sizes, int n_in,
                              void* d_out, int out_size)
{
    const float* x            = (const float*)d_in[0];
    const float* init_state   = (const float*)d_in[1];
    // d_in[2], d_in[3]: node_emb0/node_emb1 — unused by the reference
    const float* gate_align_w = (const float*)d_in[4];
    const float* gate_align_b = (const float*)d_in[5];
    const float* gate_w       = (const float*)d_in[6];
    const float* gate_b       = (const float*)d_in[7];
    const float* gate_node_w  = (const float*)d_in[8];
    const float* gate_add_w   = (const float*)d_in[9];
    const float* gate_aff_w   = (const float*)d_in[10];
    const float* gate_aff_b   = (const float*)d_in[11];
    const float* upd_align_w  = (const float*)d_in[12];
    const float* upd_align_b  = (const float*)d_in[13];
    const float* upd_w        = (const float*)d_in[14];
    const float* upd_b        = (const float*)d_in[15];
    const float* upd_node_w   = (const float*)d_in[16];
    const float* upd_add_w    = (const float*)d_in[17];
    const float* upd_aff_w    = (const float*)d_in[18];
    const float* upd_aff_b    = (const float*)d_in[19];
    float* out = (float*)d_out;

    int dyn = (KK * E2 * 2 + E2 * 2 + ROWS_TILE * 67) * (int)sizeof(float); // 77,184 B
    cudaFuncSetAttribute(k_mid, cudaFuncAttributeMaxDynamicSharedMemorySize, dyn);

    dim3 grid(CHUNKS, B);
    for (int t = 0; t < T; t++) {
        const float* state = (t == 0) ? init_state
                                      : (out + (size_t)(t - 1) * NN * H);
        int sbstride = (t == 0) ? NN * H : T * NN * H;

        k_zero<<<8, 256>>>();
        k_gate_agg<<<grid, 256>>>(x, state, sbstride, gate_w, gate_b, t);
        k_mid<<<grid, 256, dyn>>>(x, state, sbstride,
                                  gate_align_w, gate_align_b,
                                  upd_w, upd_b, upd_align_w, upd_align_b,
                                  gate_aff_w, gate_aff_b,
                                  gate_node_w, gate_add_w, t);
        k_final<<<(B * NN + 15) / 16, 256>>>(state, sbstride,
                                             upd_aff_w, upd_aff_b,
                                             upd_node_w, upd_add_w, out, t);
    }
}

// round 6
// speedup vs baseline: 1.1212x; 1.1212x over previous
#include <cuda_runtime.h>
#include <math.h>

#define B   16
#define T   12
#define NN  8600
#define H   64
#define E2  128
#define KK  66
#define RT  32                                  // rows per tile
#define NPC 128                                 // nodes per CTA
#define CHUNKS ((NN + NPC - 1) / NPC)           // 68
#define OUT_LAST_OFF ((size_t)B * T * NN * H)

// ---------------- scratch (device globals; no allocation allowed) --------------
__device__ __align__(16) float g_agg_gate[2][B * E2];
__device__ __align__(16) float g_agg_upd[2][B * H];
__device__ __align__(128) float g_r[(size_t)B * NN * H];     // gate r    (35.2 MB)
__device__ __align__(128) float g_resu[(size_t)B * NN * H];  // res_upd   (35.2 MB)

// ---------------- f32x2 helpers (packed dual-FMA) ------------------------------
__device__ __forceinline__ unsigned long long pack2(float a) {
    unsigned long long r;
    unsigned int u = __float_as_uint(a);
    asm("mov.b64 %0, {%1, %1};" : "=l"(r) : "r"(u));
    return r;
}
__device__ __forceinline__ void fma2(unsigned long long& d, unsigned long long a,
                                     unsigned long long b) {
    asm("fma.rn.f32x2 %0, %1, %2, %3;" : "=l"(d) : "l"(a), "l"(b), "l"(d));
}
__device__ __forceinline__ void unpack2(unsigned long long v, float& x, float& y) {
    asm("mov.b64 {%0, %1}, %2;" : "=f"(x), "=f"(y) : "l"(v));
}
__device__ __forceinline__ float sigmoidf_(float x) {
    return 1.0f / (1.0f + __expf(-x));
}

// 16-column dot over 66 k for one row (srow) against sW columns e0..e0+15
__device__ __forceinline__ void dot16(const float* __restrict__ srow,
                                      const float* __restrict__ sWcol,
                                      unsigned long long acc[8]) {
#pragma unroll 11
    for (int k = 0; k < KK; k++) {
        unsigned long long a2 = pack2(srow[k]);
        const ulonglong2* w2 = (const ulonglong2*)(sWcol + (size_t)k * E2);
        ulonglong2 p0 = w2[0], p1 = w2[1], p2 = w2[2], p3 = w2[3];
        fma2(acc[0], a2, p0.x); fma2(acc[1], a2, p0.y);
        fma2(acc[2], a2, p1.x); fma2(acc[3], a2, p1.y);
        fma2(acc[4], a2, p2.x); fma2(acc[5], a2, p2.y);
        fma2(acc[6], a2, p3.x); fma2(acc[7], a2, p3.y);
    }
}

// =========================== prologue zero =====================================
__global__ void k_zero0() {
    int i = blockIdx.x * blockDim.x + threadIdx.x;
    if (i < B * E2) g_agg_gate[0][i] = 0.0f;
    if (i < B * H)  g_agg_upd[0][i] = 0.0f;
}

// ========== K1 (t=0 only): relu([x,state] @ gate_w + b), agg over nodes ========
__global__ void __launch_bounds__(256) k_gate_agg(
    const float* __restrict__ x, const float* __restrict__ state, int sbstride,
    const float* __restrict__ Wg, const float* __restrict__ bg, int t, int pg)
{
    __shared__ float sW[KK * E2];
    __shared__ float sb[E2];
    __shared__ float sin_[RT * 67];

    int tid = threadIdx.x;
    int b = blockIdx.y;
    int base = blockIdx.x * NPC;

    for (int i = tid; i < KK * E2 / 4; i += 256)
        ((float4*)sW)[i] = ((const float4*)Wg)[i];
    if (tid < E2) sb[tid] = bg[tid];

    const float* xb  = x + ((size_t)(b * T + t) * NN) * 2;
    const float* stb = state + (size_t)b * sbstride;

    int sr = tid >> 3, sc = (tid & 7) * 8;        // staging: 1x 32B of state/thread
    int rl = tid & 31, e0 = (tid >> 5) * 16;      // matmul mapping

    float colsum[16];
#pragma unroll
    for (int j = 0; j < 16; j++) colsum[j] = 0.0f;

    float4 pa, pb; float px = 0.0f;
    {   // prefetch tile 0
        int n = base + sr;
        if (n < NN) {
            const float* p = stb + (size_t)n * H + sc;
            pa = *(const float4*)p; pb = *(const float4*)(p + 4);
        } else { pa = make_float4(0,0,0,0); pb = pa; }
        if (tid < 64) {
            int nx = base + (tid >> 1);
            px = (nx < NN) ? xb[(size_t)nx * 2 + (tid & 1)] : 0.0f;
        }
    }

    for (int tile = 0; tile < NPC / RT; tile++) {
        int n0 = base + tile * RT;
        __syncthreads();                           // previous matmul done with sin_
        {
            float* row = &sin_[sr * 67 + 2 + sc];
            row[0]=pa.x; row[1]=pa.y; row[2]=pa.z; row[3]=pa.w;
            row[4]=pb.x; row[5]=pb.y; row[6]=pb.z; row[7]=pb.w;
            if (tid < 64) sin_[(tid >> 1) * 67 + (tid & 1)] = px;
        }
        __syncthreads();
        if (tile < NPC / RT - 1) {                 // prefetch next tile (overlaps matmul)
            int n = n0 + RT + sr;
            if (n < NN) {
                const float* p = stb + (size_t)n * H + sc;
                pa = *(const float4*)p; pb = *(const float4*)(p + 4);
            } else { pa = make_float4(0,0,0,0); pb = pa; }
            if (tid < 64) {
                int nx = n0 + RT + (tid >> 1);
                px = (nx < NN) ? xb[(size_t)nx * 2 + (tid & 1)] : 0.0f;
            }
        }

        unsigned long long acc[8];
#pragma unroll
        for (int j = 0; j < 8; j++) acc[j] = 0ULL;
        dot16(&sin_[rl * 67], &sW[e0], acc);

        if (n0 + rl < NN) {
#pragma unroll
            for (int j = 0; j < 8; j++) {
                float v0, v1; unpack2(acc[j], v0, v1);
                colsum[2*j]   += fmaxf(v0 + sb[e0 + 2*j],     0.0f);
                colsum[2*j+1] += fmaxf(v1 + sb[e0 + 2*j + 1], 0.0f);
            }
        }
    }

#pragma unroll
    for (int j = 0; j < 16; j++) {
        float v = colsum[j];
#pragma unroll
        for (int o = 16; o > 0; o >>= 1) v += __shfl_xor_sync(0xffffffffu, v, o);
        colsum[j] = v;
    }
    if (rl == 0) {
#pragma unroll
        for (int j = 0; j < 16; j++)
            atomicAdd(&g_agg_gate[pg][b * E2 + e0 + j], colsum[j]);
    }
}

// ===== K2: sigmoid(zr) from agg_gate; cand matmuls; store r,res_upd; agg_upd ===
extern __shared__ float sdyn[];
__global__ void __launch_bounds__(256) k_mid(
    const float* __restrict__ x, const float* __restrict__ state, int sbstride,
    const float* __restrict__ Wga, const float* __restrict__ bga,
    const float* __restrict__ Wuw, const float* __restrict__ buw,
    const float* __restrict__ Wua, const float* __restrict__ bua,
    const float* __restrict__ affw, const float* __restrict__ affb,
    const float* __restrict__ nodew, const float* __restrict__ addw,
    int t, int pg, int pn)
{
    float* sWa  = sdyn;                 // gate_align_w            66x128
    float* sWu  = sWa + KK * E2;        // [upd_w | upd_align_w]   66x128
    float* sba  = sWu + KK * E2;        // 128
    float* sbu  = sba + E2;             // 128
    float* sagg = sbu + E2;             // 128 (agg_gate for this b)
    float* sin_ = sagg + E2;            // 32 x 67

    int tid = threadIdx.x;
    int b = blockIdx.y;
    int base = blockIdx.x * NPC;

    // zero next-parity agg buffers (idle this step; consumed next step)
    if (blockIdx.x == 0 && blockIdx.y == 0) {
        for (int i = tid; i < B * E2; i += 256) g_agg_gate[pn][i] = 0.0f;
        for (int i = tid; i < B * H;  i += 256) g_agg_upd[pn][i] = 0.0f;
    }

    for (int i = tid; i < KK * E2 / 4; i += 256)
        ((float4*)sWa)[i] = ((const float4*)Wga)[i];
    for (int i = tid; i < KK * H / 4; i += 256) {
        int k = i / (H / 4), g = i % (H / 4);
        ((float4*)sWu)[k * 32 + g]      = ((const float4*)Wuw)[i];
        ((float4*)sWu)[k * 32 + 16 + g] = ((const float4*)Wua)[i];
    }
    if (tid < E2) {
        sba[tid]  = bga[tid];
        sbu[tid]  = (tid < H) ? buw[tid] : bua[tid - H];
        sagg[tid] = g_agg_gate[pg][b * E2 + tid];
    }

    const float* xb  = x + ((size_t)(b * T + t) * NN) * 2;
    const float* stb = state + (size_t)b * sbstride;

    int sr = tid >> 3, sc = (tid & 7) * 8;
    int rl = tid & 31, eg = tid >> 5, e0 = eg * 16;

    float colsum[16];
#pragma unroll
    for (int j = 0; j < 16; j++) colsum[j] = 0.0f;

    float4 pa, pb; float px = 0.0f;
    {
        int n = base + sr;
        if (n < NN) {
            const float* p = stb + (size_t)n * H + sc;
            pa = *(const float4*)p; pb = *(const float4*)(p + 4);
        } else { pa = make_float4(0,0,0,0); pb = pa; }
        if (tid < 64) {
            int nx = base + (tid >> 1);
            px = (nx < NN) ? xb[(size_t)nx * 2 + (tid & 1)] : 0.0f;
        }
    }

    for (int tile = 0; tile < NPC / RT; tile++) {
        int n0 = base + tile * RT;
        __syncthreads();
        {
            float* row = &sin_[sr * 67 + 2 + sc];
            row[0]=pa.x; row[1]=pa.y; row[2]=pa.z; row[3]=pa.w;
            row[4]=pb.x; row[5]=pb.y; row[6]=pb.z; row[7]=pb.w;
            if (tid < 64) sin_[(tid >> 1) * 67 + (tid & 1)] = px;
        }
        __syncthreads();
        if (tile < NPC / RT - 1) {
            int n = n0 + RT + sr;
            if (n < NN) {
                const float* p = stb + (size_t)n * H + sc;
                pa = *(const float4*)p; pb = *(const float4*)(p + 4);
            } else { pa = make_float4(0,0,0,0); pb = pa; }
            if (tid < 64) {
                int nx = n0 + RT + (tid >> 1);
                px = (nx < NN) ? xb[(size_t)nx * 2 + (tid & 1)] : 0.0f;
            }
        }

        int n = n0 + rl;
        bool valid = (n < NN);
        const float* srow = &sin_[rl * 67];

        // ---- gate-align dot + sigmoid ----
        unsigned long long acc[8];
#pragma unroll
        for (int j = 0; j < 8; j++) acc[j] = 0ULL;
        dot16(srow, &sWa[e0], acc);

        float zr[16];
        {
            float sgn = 0.0f;
            float aw[16], ab[16];
#pragma unroll
            for (int j = 0; j < 16; j++) { aw[j] = 0.0f; ab[j] = 0.0f; }
            if (valid) {
                sgn = addw[n] * nodew[n];
                const float4* awp = (const float4*)&affw[(size_t)n * E2 + e0];
                const float4* abp = (const float4*)&affb[(size_t)n * E2 + e0];
#pragma unroll
                for (int q = 0; q < 4; q++) {
                    ((float4*)aw)[q] = awp[q];
                    ((float4*)ab)[q] = abp[q];
                }
            }
#pragma unroll
            for (int j = 0; j < 8; j++) {
                float v0, v1; unpack2(acc[j], v0, v1);
                float p0 = v0 + sba[e0 + 2*j];
                float p1 = v1 + sba[e0 + 2*j + 1];
                p0 += aw[2*j]   * sgn * sagg[e0 + 2*j]     + ab[2*j];
                p1 += aw[2*j+1] * sgn * sagg[e0 + 2*j + 1] + ab[2*j+1];
                zr[2*j]   = sigmoidf_(p0);
                zr[2*j+1] = sigmoidf_(p1);
            }
        }

        __syncthreads();                 // all reads of sin_ (align matmul) done
        if (eg < 4) {                    // z: cand state = z * state, in place
#pragma unroll
            for (int j = 0; j < 16; j++)
                sin_[rl * 67 + 2 + e0 + j] *= zr[j];
        } else if (valid) {              // r: store for finalize
            float* rp = &g_r[((size_t)b * NN + n) * H + (e0 - 64)];
            ((float4*)rp)[0] = make_float4(zr[0], zr[1], zr[2], zr[3]);
            ((float4*)rp)[1] = make_float4(zr[4], zr[5], zr[6], zr[7]);
            ((float4*)rp)[2] = make_float4(zr[8], zr[9], zr[10], zr[11]);
            ((float4*)rp)[3] = make_float4(zr[12], zr[13], zr[14], zr[15]);
        }
        __syncthreads();

        // ---- update dot: cols 0..63 relu+agg, cols 64..127 res_upd ----
#pragma unroll
        for (int j = 0; j < 8; j++) acc[j] = 0ULL;
        dot16(srow, &sWu[e0], acc);

        if (eg < 4) {
            if (valid) {
#pragma unroll
                for (int j = 0; j < 8; j++) {
                    float v0, v1; unpack2(acc[j], v0, v1);
                    colsum[2*j]   += fmaxf(v0 + sbu[e0 + 2*j],     0.0f);
                    colsum[2*j+1] += fmaxf(v1 + sbu[e0 + 2*j + 1], 0.0f);
                }
            }
        } else if (valid) {
            float ru[16];
#pragma unroll
            for (int j = 0; j < 8; j++) {
                float v0, v1; unpack2(acc[j], v0, v1);
                ru[2*j]   = v0 + sbu[e0 + 2*j];
                ru[2*j+1] = v1 + sbu[e0 + 2*j + 1];
            }
            float* rp = &g_resu[((size_t)b * NN + n) * H + (e0 - 64)];
            ((float4*)rp)[0] = make_float4(ru[0], ru[1], ru[2], ru[3]);
            ((float4*)rp)[1] = make_float4(ru[4], ru[5], ru[6], ru[7]);
            ((float4*)rp)[2] = make_float4(ru[8], ru[9], ru[10], ru[11]);
            ((float4*)rp)[3] = make_float4(ru[12], ru[13], ru[14], ru[15]);
        }
    }

    if (eg < 4) {  // warp-uniform
#pragma unroll
        for (int j = 0; j < 16; j++) {
            float v = colsum[j];
#pragma unroll
            for (int o = 16; o > 0; o >>= 1) v += __shfl_xor_sync(0xffffffffu, v, o);
            colsum[j] = v;
        }
        if (rl == 0) {
#pragma unroll
            for (int j = 0; j < 16; j++)
                atomicAdd(&g_agg_upd[pg][b * H + e0 + j], colsum[j]);
        }
    }
}

// ===== K3': finalize h, write out, AND compute next step's gate matmul + agg ===
__global__ void __launch_bounds__(256) k_final2(
    const float* __restrict__ state, int sbstride,
    const float* __restrict__ x,                  // for t+1 staging (if do_gate)
    const float* __restrict__ Wg, const float* __restrict__ bg,
    const float* __restrict__ affw, const float* __restrict__ affb,
    const float* __restrict__ nodew, const float* __restrict__ addw,
    float* __restrict__ out, int t, int pu, int pgn, int do_gate)
{
    __shared__ float sW[KK * E2];
    __shared__ float sb[E2];
    __shared__ float sin_[RT * 67];

    int tid = threadIdx.x;
    int b = blockIdx.y;
    int base = blockIdx.x * NPC;

    if (do_gate) {
        for (int i = tid; i < KK * E2 / 4; i += 256)
            ((float4*)sW)[i] = ((const float4*)Wg)[i];
        if (tid < E2) sb[tid] = bg[tid];
    }

    int hr = tid >> 3, hc = (tid & 7) * 8;        // h phase: 32 rows x 8 cols
    int rl = tid & 31, e0 = (tid >> 5) * 16;      // matmul mapping

    const float* stb = state + (size_t)b * sbstride;
    const float* xb  = x + ((size_t)(b * T + (t + 1)) * NN) * 2;  // only if do_gate

    float ag[8];
#pragma unroll
    for (int j = 0; j < 8; j++) ag[j] = g_agg_upd[pu][b * H + hc + j];

    float colsum[16];
#pragma unroll
    for (int j = 0; j < 16; j++) colsum[j] = 0.0f;

    for (int tile = 0; tile < NPC / RT; tile++) {
        int n0 = base + tile * RT;
        int n = n0 + hr;
        bool v = (n < NN);

        float h8[8];
#pragma unroll
        for (int j = 0; j < 8; j++) h8[j] = 0.0f;

        if (v) {
            size_t ro = ((size_t)b * NN + n) * H + hc;
            float4 r0 = ((const float4*)&g_r[ro])[0];
            float4 r1 = ((const float4*)&g_r[ro])[1];
            float4 u0 = ((const float4*)&g_resu[ro])[0];
            float4 u1 = ((const float4*)&g_resu[ro])[1];
            const float* sp = stb + (size_t)n * H + hc;
            float4 s0 = ((const float4*)sp)[0];
            float4 s1 = ((const float4*)sp)[1];
            float su = addw[n] * nodew[n];
            const float* ap = affw + (size_t)n * H + hc;
            const float* bp = affb + (size_t)n * H + hc;
            float4 a0 = ((const float4*)ap)[0];
            float4 a1 = ((const float4*)ap)[1];
            float4 c0 = ((const float4*)bp)[0];
            float4 c1 = ((const float4*)bp)[1];

            h8[0] = r0.x*s0.x + (1.0f-r0.x)*tanhf(u0.x + a0.x*su*ag[0] + c0.x);
            h8[1] = r0.y*s0.y + (1.0f-r0.y)*tanhf(u0.y + a0.y*su*ag[1] + c0.y);
            h8[2] = r0.z*s0.z + (1.0f-r0.z)*tanhf(u0.z + a0.z*su*ag[2] + c0.z);
            h8[3] = r0.w*s0.w + (1.0f-r0.w)*tanhf(u0.w + a0.w*su*ag[3] + c0.w);
            h8[4] = r1.x*s1.x + (1.0f-r1.x)*tanhf(u1.x + a1.x*su*ag[4] + c1.x);
            h8[5] = r1.y*s1.y + (1.0f-r1.y)*tanhf(u1.y + a1.y*su*ag[5] + c1.y);
            h8[6] = r1.z*s1.z + (1.0f-r1.z)*tanhf(u1.z + a1.z*su*ag[6] + c1.z);
            h8[7] = r1.w*s1.w + (1.0f-r1.w)*tanhf(u1.w + a1.w*su*ag[7] + c1.w);

            float4 o0 = make_float4(h8[0], h8[1], h8[2], h8[3]);
            float4 o1 = make_float4(h8[4], h8[5], h8[6], h8[7]);
            float* op = out + ((size_t)(b * T + t) * NN + n) * H + hc;
            ((float4*)op)[0] = o0; ((float4*)op)[1] = o1;
            if (t == T - 1) {
                float* lp = out + OUT_LAST_OFF + ((size_t)b * NN + n) * H + hc;
                ((float4*)lp)[0] = o0; ((float4*)lp)[1] = o1;
            }
        }

        if (do_gate) {
            __syncthreads();                       // previous matmul done with sin_
            float* row = &sin_[hr * 67 + 2 + hc];
#pragma unroll
            for (int j = 0; j < 8; j++) row[j] = h8[j];
            if (tid < 64) {
                int nx = n0 + (tid >> 1);
                sin_[(tid >> 1) * 67 + (tid & 1)] =
                    (nx < NN) ? xb[(size_t)nx * 2 + (tid & 1)] : 0.0f;
            }
            __syncthreads();

            unsigned long long acc[8];
#pragma unroll
            for (int j = 0; j < 8; j++) acc[j] = 0ULL;
            dot16(&sin_[rl * 67], &sW[e0], acc);

            if (n0 + rl < NN) {
#pragma unroll
                for (int j = 0; j < 8; j++) {
                    float v0, v1; unpack2(acc[j], v0, v1);
                    colsum[2*j]   += fmaxf(v0 + sb[e0 + 2*j],     0.0f);
                    colsum[2*j+1] += fmaxf(v1 + sb[e0 + 2*j + 1], 0.0f);
                }
            }
        }
    }

    if (do_gate) {
#pragma unroll
        for (int j = 0; j < 16; j++) {
            float v = colsum[j];
#pragma unroll
            for (int o = 16; o > 0; o >>= 1) v += __shfl_xor_sync(0xffffffffu, v, o);
            colsum[j] = v;
        }
        if (rl == 0) {
#pragma unroll
            for (int j = 0; j < 16; j++)
                atomicAdd(&g_agg_gate[pgn][b * E2 + e0 + j], colsum[j]);
        }
    }
}

// =============================== launch ========================================
extern "C" void kernel_launch(void* const* d_in, const int* in_sizes, int n_in,
                              void* d_out, int out_size)
{
    const float* x            = (const float*)d_in[0];
    const float* init_state   = (const float*)d_in[1];
    // d_in[2], d_in[3]: node_emb0/node_emb1 — unused by the reference
    const float* gate_align_w = (const float*)d_in[4];
    const float* gate_align_b = (const float*)d_in[5];
    const float* gate_w       = (const float*)d_in[6];
    const float* gate_b       = (const float*)d_in[7];
    const float* gate_node_w  = (const float*)d_in[8];
    const float* gate_add_w   = (const float*)d_in[9];
    const float* gate_aff_w   = (const float*)d_in[10];
    const float* gate_aff_b   = (const float*)d_in[11];
    const float* upd_align_w  = (const float*)d_in[12];
    const float* upd_align_b  = (const float*)d_in[13];
    const float* upd_w        = (const float*)d_in[14];
    const float* upd_b        = (const float*)d_in[15];
    const float* upd_node_w   = (const float*)d_in[16];
    const float* upd_add_w    = (const float*)d_in[17];
    const float* upd_aff_w    = (const float*)d_in[18];
    const float* upd_aff_b    = (const float*)d_in[19];
    float* out = (float*)d_out;

    int dyn = (KK * E2 * 2 + E2 * 3 + RT * 67) * (int)sizeof(float); // 77,696 B
    cudaFuncSetAttribute(k_mid, cudaFuncAttributeMaxDynamicSharedMemorySize, dyn);

    dim3 grid(CHUNKS, B);

    k_zero0<<<8, 256>>>();
    k_gate_agg<<<grid, 256>>>(x, init_state, NN * H, gate_w, gate_b, 0, 0);

    for (int t = 0; t < T; t++) {
        const float* state = (t == 0) ? init_state
                                      : (out + (size_t)(t - 1) * NN * H);
        int sstr = (t == 0) ? NN * H : T * NN * H;

        k_mid<<<grid, 256, dyn>>>(x, state, sstr,
                                  gate_align_w, gate_align_b,
                                  upd_w, upd_b, upd_align_w, upd_align_b,
                                  gate_aff_w, gate_aff_b,
                                  gate_node_w, gate_add_w,
                                  t, t & 1, (t + 1) & 1);

        k_final2<<<grid, 256>>>(state, sstr, x, gate_w, gate_b,
                                upd_aff_w, upd_aff_b,
                                upd_node_w, upd_add_w,
                                out, t, t & 1, (t + 1) & 1,
                                (t < T - 1) ? 1 : 0);
    }
}

// round 8
// speedup vs baseline: 1.1422x; 1.0187x over previous
#include <cuda_runtime.h>
#include <math.h>

#define B   16
#define T   12
#define NN  8600
#define H   64
#define E2  128
#define KK  66
#define RT  32                                  // rows per tile
#define NPC 128                                 // nodes per CTA
#define CHUNKS ((NN + NPC - 1) / NPC)           // 68
#define OUT_LAST_OFF ((size_t)B * T * NN * H)

// ---------------- scratch (device globals; no allocation allowed) --------------
__device__ __align__(16) float g_agg_gate[2][B * E2];
__device__ __align__(16) float g_agg_upd[2][B * H];
__device__ __align__(128) float g_r[(size_t)B * NN * H];     // gate r    (35.2 MB)
__device__ __align__(128) float g_resu[(size_t)B * NN * H];  // res_upd   (35.2 MB)

// ---------------- f32x2 helpers (packed dual-FMA) ------------------------------
__device__ __forceinline__ unsigned long long pack2(float a) {
    unsigned long long r;
    unsigned int u = __float_as_uint(a);
    asm("mov.b64 %0, {%1, %1};" : "=l"(r) : "r"(u));
    return r;
}
__device__ __forceinline__ void fma2(unsigned long long& d, unsigned long long a,
                                     unsigned long long b) {
    asm("fma.rn.f32x2 %0, %1, %2, %3;" : "=l"(d) : "l"(a), "l"(b), "l"(d));
}
__device__ __forceinline__ void unpack2(unsigned long long v, float& x, float& y) {
    asm("mov.b64 {%0, %1}, %2;" : "=f"(x), "=f"(y) : "l"(v));
}
__device__ __forceinline__ float sigmoidf_(float x) {
    return 1.0f / (1.0f + __expf(-x));
}

// 16-column dot over 66 k for one row (srow) against sW columns e0..e0+15
__device__ __forceinline__ void dot16(const float* __restrict__ srow,
                                      const float* __restrict__ sWcol,
                                      unsigned long long acc[8]) {
#pragma unroll 11
    for (int k = 0; k < KK; k++) {
        unsigned long long a2 = pack2(srow[k]);
        const ulonglong2* w2 = (const ulonglong2*)(sWcol + (size_t)k * E2);
        ulonglong2 p0 = w2[0], p1 = w2[1], p2 = w2[2], p3 = w2[3];
        fma2(acc[0], a2, p0.x); fma2(acc[1], a2, p0.y);
        fma2(acc[2], a2, p1.x); fma2(acc[3], a2, p1.y);
        fma2(acc[4], a2, p2.x); fma2(acc[5], a2, p2.y);
        fma2(acc[6], a2, p3.x); fma2(acc[7], a2, p3.y);
    }
}

// =========================== prologue zero =====================================
__global__ void k_zero0() {
    int i = blockIdx.x * blockDim.x + threadIdx.x;
    if (i < B * E2) g_agg_gate[0][i] = 0.0f;
    if (i < B * H)  g_agg_upd[0][i] = 0.0f;
}

// ========== K1 (t=0 only): relu([x,state] @ gate_w + b), agg over nodes ========
__global__ void __launch_bounds__(256) k_gate_agg(
    const float* __restrict__ x, const float* __restrict__ state, int sbstride,
    const float* __restrict__ Wg, const float* __restrict__ bg, int t, int pg)
{
    __shared__ __align__(16) float sW[KK * E2];
    __shared__ float sb[E2];
    __shared__ __align__(16) float sin_[RT * 67];

    int tid = threadIdx.x;
    int b = blockIdx.y;
    int base = blockIdx.x * NPC;

    for (int i = tid; i < KK * E2 / 4; i += 256)
        ((float4*)sW)[i] = ((const float4*)Wg)[i];
    if (tid < E2) sb[tid] = bg[tid];

    const float* xb  = x + ((size_t)(b * T + t) * NN) * 2;
    const float* stb = state + (size_t)b * sbstride;

    int sr = tid >> 3, sc = (tid & 7) * 8;
    int rl = tid & 31, e0 = (tid >> 5) * 16;

    float colsum[16];
#pragma unroll
    for (int j = 0; j < 16; j++) colsum[j] = 0.0f;

    float4 pa, pb; float px = 0.0f;
    {
        int n = base + sr;
        if (n < NN) {
            const float* p = stb + (size_t)n * H + sc;
            pa = *(const float4*)p; pb = *(const float4*)(p + 4);
        } else { pa = make_float4(0,0,0,0); pb = pa; }
        if (tid < 64) {
            int nx = base + (tid >> 1);
            px = (nx < NN) ? xb[(size_t)nx * 2 + (tid & 1)] : 0.0f;
        }
    }

    for (int tile = 0; tile < NPC / RT; tile++) {
        int n0 = base + tile * RT;
        __syncthreads();
        {
            float* row = &sin_[sr * 67 + 2 + sc];
            row[0]=pa.x; row[1]=pa.y; row[2]=pa.z; row[3]=pa.w;
            row[4]=pb.x; row[5]=pb.y; row[6]=pb.z; row[7]=pb.w;
            if (tid < 64) sin_[(tid >> 1) * 67 + (tid & 1)] = px;
        }
        __syncthreads();
        if (tile < NPC / RT - 1) {
            int n = n0 + RT + sr;
            if (n < NN) {
                const float* p = stb + (size_t)n * H + sc;
                pa = *(const float4*)p; pb = *(const float4*)(p + 4);
            } else { pa = make_float4(0,0,0,0); pb = pa; }
            if (tid < 64) {
                int nx = n0 + RT + (tid >> 1);
                px = (nx < NN) ? xb[(size_t)nx * 2 + (tid & 1)] : 0.0f;
            }
        }

        unsigned long long acc[8];
#pragma unroll
        for (int j = 0; j < 8; j++) acc[j] = 0ULL;
        dot16(&sin_[rl * 67], &sW[e0], acc);

        if (n0 + rl < NN) {
#pragma unroll
            for (int j = 0; j < 8; j++) {
                float v0, v1; unpack2(acc[j], v0, v1);
                colsum[2*j]   += fmaxf(v0 + sb[e0 + 2*j],     0.0f);
                colsum[2*j+1] += fmaxf(v1 + sb[e0 + 2*j + 1], 0.0f);
            }
        }
    }

#pragma unroll
    for (int j = 0; j < 16; j++) {
        float v = colsum[j];
#pragma unroll
        for (int o = 16; o > 0; o >>= 1) v += __shfl_xor_sync(0xffffffffu, v, o);
        colsum[j] = v;
    }
    if (rl == 0) {
#pragma unroll
        for (int j = 0; j < 16; j++)
            atomicAdd(&g_agg_gate[pg][b * E2 + e0 + j], colsum[j]);
    }
}

// ===== K2: sigmoid(zr) from agg_gate; cand matmuls; store r,res_upd; agg_upd ===
extern __shared__ float sdyn[];
__global__ void __launch_bounds__(256, 2) k_mid(
    const float* __restrict__ x, const float* __restrict__ state, int sbstride,
    const float* __restrict__ Wga, const float* __restrict__ bga,
    const float* __restrict__ Wuw, const float* __restrict__ buw,
    const float* __restrict__ Wua, const float* __restrict__ bua,
    const float* __restrict__ affw, const float* __restrict__ affb,
    const float* __restrict__ nodew, const float* __restrict__ addw,
    int t, int pg, int pn)
{
    float* sWa  = sdyn;                 // gate_align_w            66x128
    float* sWu  = sWa + KK * E2;        // [upd_w | upd_align_w]   66x128
    float* sba  = sWu + KK * E2;        // 128
    float* sbu  = sba + E2;             // 128
    float* sagg = sbu + E2;             // 128
    float* sin_ = sagg + E2;            // 32 x 67  ([x, state])
    float* sin2 = sin_ + RT * 67;       // 32 x 67  ([x, z*state])

    int tid = threadIdx.x;
    int b = blockIdx.y;
    int base = blockIdx.x * NPC;

    // zero next-parity agg buffers (consumed next step)
    if (blockIdx.x == 0 && blockIdx.y == 0) {
        for (int i = tid; i < B * E2; i += 256) g_agg_gate[pn][i] = 0.0f;
        for (int i = tid; i < B * H;  i += 256) g_agg_upd[pn][i] = 0.0f;
    }

    for (int i = tid; i < KK * E2 / 4; i += 256)
        ((float4*)sWa)[i] = ((const float4*)Wga)[i];
    for (int i = tid; i < KK * H / 4; i += 256) {
        int k = i / (H / 4), g = i % (H / 4);
        ((float4*)sWu)[k * 32 + g]      = ((const float4*)Wuw)[i];
        ((float4*)sWu)[k * 32 + 16 + g] = ((const float4*)Wua)[i];
    }
    if (tid < E2) {
        sba[tid]  = bga[tid];
        sbu[tid]  = (tid < H) ? buw[tid] : bua[tid - H];
        sagg[tid] = g_agg_gate[pg][b * E2 + tid];
    }

    const float* xb  = x + ((size_t)(b * T + t) * NN) * 2;
    const float* stb = state + (size_t)b * sbstride;

    int sr = tid >> 3, sc = (tid & 7) * 8;
    int rl = tid & 31, eg = tid >> 5, e0 = eg * 16;

    float colsum[16];
#pragma unroll
    for (int j = 0; j < 16; j++) colsum[j] = 0.0f;

    // ---- prefetch tile 0: state rows, x, and aff(w/b)+sgn for this lane's row
    float4 pa, pb; float px = 0.0f;
    float aw[16], ab[16]; float sgn = 0.0f;
    {
        int n = base + sr;
        if (n < NN) {
            const float* p = stb + (size_t)n * H + sc;
            pa = *(const float4*)p; pb = *(const float4*)(p + 4);
        } else { pa = make_float4(0,0,0,0); pb = pa; }
        if (tid < 64) {
            int nx = base + (tid >> 1);
            px = (nx < NN) ? xb[(size_t)nx * 2 + (tid & 1)] : 0.0f;
        }
        int na = base + rl;
#pragma unroll
        for (int j = 0; j < 16; j++) { aw[j] = 0.0f; ab[j] = 0.0f; }
        if (na < NN) {
            sgn = addw[na] * nodew[na];
            const float4* awp = (const float4*)&affw[(size_t)na * E2 + e0];
            const float4* abp = (const float4*)&affb[(size_t)na * E2 + e0];
#pragma unroll
            for (int q = 0; q < 4; q++) {
                ((float4*)aw)[q] = awp[q];
                ((float4*)ab)[q] = abp[q];
            }
        }
    }

    for (int tile = 0; tile < NPC / RT; tile++) {
        int n0 = base + tile * RT;
        __syncthreads();                          // S1: prev tile fully done
        {
            float* row = &sin_[sr * 67 + 2 + sc];
            row[0]=pa.x; row[1]=pa.y; row[2]=pa.z; row[3]=pa.w;
            row[4]=pb.x; row[5]=pb.y; row[6]=pb.z; row[7]=pb.w;
            if (tid < 64) {
                sin_[(tid >> 1) * 67 + (tid & 1)] = px;
                sin2[(tid >> 1) * 67 + (tid & 1)] = px;
            }
        }
        __syncthreads();                          // S2: staging visible
        if (tile < NPC / RT - 1) {                // prefetch next state+x (overlaps align matmul)
            int n = n0 + RT + sr;
            if (n < NN) {
                const float* p = stb + (size_t)n * H + sc;
                pa = *(const float4*)p; pb = *(const float4*)(p + 4);
            } else { pa = make_float4(0,0,0,0); pb = pa; }
            if (tid < 64) {
                int nx = n0 + RT + (tid >> 1);
                px = (nx < NN) ? xb[(size_t)nx * 2 + (tid & 1)] : 0.0f;
            }
        }

        int n = n0 + rl;
        bool valid = (n < NN);
        const float* srow = &sin_[rl * 67];

        // ---- gate-align dot + sigmoid (uses prefetched aff) ----
        unsigned long long acc[8];
#pragma unroll
        for (int j = 0; j < 8; j++) acc[j] = 0ULL;
        dot16(srow, &sWa[e0], acc);

        float zr[16];
#pragma unroll
        for (int j = 0; j < 8; j++) {
            float v0, v1; unpack2(acc[j], v0, v1);
            float p0 = v0 + sba[e0 + 2*j];
            float p1 = v1 + sba[e0 + 2*j + 1];
            p0 += aw[2*j]   * sgn * sagg[e0 + 2*j]     + ab[2*j];
            p1 += aw[2*j+1] * sgn * sagg[e0 + 2*j + 1] + ab[2*j+1];
            zr[2*j]   = sigmoidf_(p0);
            zr[2*j+1] = sigmoidf_(p1);
        }

        // prefetch next tile's aff (aw/ab now free; overlaps update matmul)
        if (tile < NPC / RT - 1) {
            int na = n0 + RT + rl;
            sgn = 0.0f;
#pragma unroll
            for (int j = 0; j < 16; j++) { aw[j] = 0.0f; ab[j] = 0.0f; }
            if (na < NN) {
                sgn = addw[na] * nodew[na];
                const float4* awp = (const float4*)&affw[(size_t)na * E2 + e0];
                const float4* abp = (const float4*)&affb[(size_t)na * E2 + e0];
#pragma unroll
                for (int q = 0; q < 4; q++) {
                    ((float4*)aw)[q] = awp[q];
                    ((float4*)ab)[q] = abp[q];
                }
            }
        }

        // z: write cand = z*state into sin2 (no extra barrier; different buffer)
        if (eg < 4) {
#pragma unroll
            for (int j = 0; j < 16; j++)
                sin2[rl * 67 + 2 + e0 + j] = zr[j] * sin_[rl * 67 + 2 + e0 + j];
        } else if (valid) {
            float* rp = &g_r[((size_t)b * NN + n) * H + (e0 - 64)];
            ((float4*)rp)[0] = make_float4(zr[0], zr[1], zr[2], zr[3]);
            ((float4*)rp)[1] = make_float4(zr[4], zr[5], zr[6], zr[7]);
            ((float4*)rp)[2] = make_float4(zr[8], zr[9], zr[10], zr[11]);
            ((float4*)rp)[3] = make_float4(zr[12], zr[13], zr[14], zr[15]);
        }
        __syncthreads();                          // S3: sin2 complete

        // ---- update dot: cols 0..63 relu+agg, cols 64..127 res_upd ----
#pragma unroll
        for (int j = 0; j < 8; j++) acc[j] = 0ULL;
        dot16(&sin2[rl * 67], &sWu[e0], acc);

        if (eg < 4) {
            if (valid) {
#pragma unroll
                for (int j = 0; j < 8; j++) {
                    float v0, v1; unpack2(acc[j], v0, v1);
                    colsum[2*j]   += fmaxf(v0 + sbu[e0 + 2*j],     0.0f);
                    colsum[2*j+1] += fmaxf(v1 + sbu[e0 + 2*j + 1], 0.0f);
                }
            }
        } else if (valid) {
            float ru[16];
#pragma unroll
            for (int j = 0; j < 8; j++) {
                float v0, v1; unpack2(acc[j], v0, v1);
                ru[2*j]   = v0 + sbu[e0 + 2*j];
                ru[2*j+1] = v1 + sbu[e0 + 2*j + 1];
            }
            float* rp = &g_resu[((size_t)b * NN + n) * H + (e0 - 64)];
            ((float4*)rp)[0] = make_float4(ru[0], ru[1], ru[2], ru[3]);
            ((float4*)rp)[1] = make_float4(ru[4], ru[5], ru[6], ru[7]);
            ((float4*)rp)[2] = make_float4(ru[8], ru[9], ru[10], ru[11]);
            ((float4*)rp)[3] = make_float4(ru[12], ru[13], ru[14], ru[15]);
        }
    }

    if (eg < 4) {  // warp-uniform
#pragma unroll
        for (int j = 0; j < 16; j++) {
            float v = colsum[j];
#pragma unroll
            for (int o = 16; o > 0; o >>= 1) v += __shfl_xor_sync(0xffffffffu, v, o);
            colsum[j] = v;
        }
        if (rl == 0) {
#pragma unroll
            for (int j = 0; j < 16; j++)
                atomicAdd(&g_agg_upd[pg][b * H + e0 + j], colsum[j]);
        }
    }
}

// ===== K3: phase1 = h for all 4 tiles (barrier-free, big MLP); phase2 = gate ===
__global__ void __launch_bounds__(256, 2) k_final2(
    const float* __restrict__ state, int sbstride,
    const float* __restrict__ x,                  // for t+1 staging (if do_gate)
    const float* __restrict__ Wg, const float* __restrict__ bg,
    const float* __restrict__ affw, const float* __restrict__ affb,
    const float* __restrict__ nodew, const float* __restrict__ addw,
    float* __restrict__ out, int t, int pu, int pgn, int do_gate)
{
    __shared__ __align__(16) float sW[KK * E2];
    __shared__ float sb[E2];
    __shared__ __align__(16) float sin_[RT * 67];

    int tid = threadIdx.x;
    int b = blockIdx.y;
    int base = blockIdx.x * NPC;

    if (do_gate) {
        for (int i = tid; i < KK * E2 / 4; i += 256)
            ((float4*)sW)[i] = ((const float4*)Wg)[i];
        if (tid < E2) sb[tid] = bg[tid];
    }

    int hr = tid >> 3, hc = (tid & 7) * 8;        // h phase: 32 rows x 8 cols
    int rl = tid & 31, e0 = (tid >> 5) * 16;      // matmul mapping

    const float* stb = state + (size_t)b * sbstride;
    const float* xb  = x + ((size_t)(b * T + (t + 1)) * NN) * 2;

    float ag[8];
#pragma unroll
    for (int j = 0; j < 8; j++) ag[j] = g_agg_upd[pu][b * H + hc + j];

    // -------- phase 1: compute h for all 4 tiles, no barriers, deep MLP --------
    float h_all[4][8];
    float px[4] = {0.0f, 0.0f, 0.0f, 0.0f};

#pragma unroll
    for (int tile = 0; tile < NPC / RT; tile++) {
        int n = base + tile * RT + hr;
#pragma unroll
        for (int j = 0; j < 8; j++) h_all[tile][j] = 0.0f;

        if (n < NN) {
            size_t ro = ((size_t)b * NN + n) * H + hc;
            float4 r0 = ((const float4*)&g_r[ro])[0];
            float4 r1 = ((const float4*)&g_r[ro])[1];
            float4 u0 = ((const float4*)&g_resu[ro])[0];
            float4 u1 = ((const float4*)&g_resu[ro])[1];
            const float* sp = stb + (size_t)n * H + hc;
            float4 s0 = ((const float4*)sp)[0];
            float4 s1 = ((const float4*)sp)[1];
            float su = addw[n] * nodew[n];
            const float* ap = affw + (size_t)n * H + hc;
            const float* bp = affb + (size_t)n * H + hc;
            float4 a0 = ((const float4*)ap)[0];
            float4 a1 = ((const float4*)ap)[1];
            float4 c0 = ((const float4*)bp)[0];
            float4 c1 = ((const float4*)bp)[1];

            h_all[tile][0] = r0.x*s0.x + (1.0f-r0.x)*tanhf(u0.x + a0.x*su*ag[0] + c0.x);
            h_all[tile][1] = r0.y*s0.y + (1.0f-r0.y)*tanhf(u0.y + a0.y*su*ag[1] + c0.y);
            h_all[tile][2] = r0.z*s0.z + (1.0f-r0.z)*tanhf(u0.z + a0.z*su*ag[2] + c0.z);
            h_all[tile][3] = r0.w*s0.w + (1.0f-r0.w)*tanhf(u0.w + a0.w*su*ag[3] + c0.w);
            h_all[tile][4] = r1.x*s1.x + (1.0f-r1.x)*tanhf(u1.x + a1.x*su*ag[4] + c1.x);
            h_all[tile][5] = r1.y*s1.y + (1.0f-r1.y)*tanhf(u1.y + a1.y*su*ag[5] + c1.y);
            h_all[tile][6] = r1.z*s1.z + (1.0f-r1.z)*tanhf(u1.z + a1.z*su*ag[6] + c1.z);
            h_all[tile][7] = r1.w*s1.w + (1.0f-r1.w)*tanhf(u1.w + a1.w*su*ag[7] + c1.w);

            float4 o0 = make_float4(h_all[tile][0], h_all[tile][1],
                                    h_all[tile][2], h_all[tile][3]);
            float4 o1 = make_float4(h_all[tile][4], h_all[tile][5],
                                    h_all[tile][6], h_all[tile][7]);
            float* op = out + ((size_t)(b * T + t) * NN + n) * H + hc;
            ((float4*)op)[0] = o0; ((float4*)op)[1] = o1;
            if (t == T - 1) {
                float* lp = out + OUT_LAST_OFF + ((size_t)b * NN + n) * H + hc;
                ((float4*)lp)[0] = o0; ((float4*)lp)[1] = o1;
            }
        }
        if (do_gate && tid < 64) {
            int nx = base + tile * RT + (tid >> 1);
            px[tile] = (nx < NN) ? xb[(size_t)nx * 2 + (tid & 1)] : 0.0f;
        }
    }

    if (!do_gate) return;

    // -------- phase 2: gate matmul for t+1, staged purely from registers -------
    float colsum[16];
#pragma unroll
    for (int j = 0; j < 16; j++) colsum[j] = 0.0f;

    for (int tile = 0; tile < NPC / RT; tile++) {
        __syncthreads();                           // prev matmul done with sin_
        {
            float* row = &sin_[hr * 67 + 2 + hc];
#pragma unroll
            for (int j = 0; j < 8; j++) row[j] = h_all[tile][j];
            if (tid < 64) sin_[(tid >> 1) * 67 + (tid & 1)] = px[tile];
        }
        __syncthreads();

        unsigned long long acc[8];
#pragma unroll
        for (int j = 0; j < 8; j++) acc[j] = 0ULL;
        dot16(&sin_[rl * 67], &sW[e0], acc);

        if (base + tile * RT + rl < NN) {
#pragma unroll
            for (int j = 0; j < 8; j++) {
                float v0, v1; unpack2(acc[j], v0, v1);
                colsum[2*j]   += fmaxf(v0 + sb[e0 + 2*j],     0.0f);
                colsum[2*j+1] += fmaxf(v1 + sb[e0 + 2*j + 1], 0.0f);
            }
        }
    }

#pragma unroll
    for (int j = 0; j < 16; j++) {
        float v = colsum[j];
#pragma unroll
        for (int o = 16; o > 0; o >>= 1) v += __shfl_xor_sync(0xffffffffu, v, o);
        colsum[j] = v;
    }
    if (rl == 0) {
#pragma unroll
        for (int j = 0; j < 16; j++)
            atomicAdd(&g_agg_gate[pgn][b * E2 + e0 + j], colsum[j]);
    }
}

// =============================== launch ========================================
extern "C" void kernel_launch(void* const* d_in, const int* in_sizes, int n_in,
                              void* d_out, int out_size)
{
    const float* x            = (const float*)d_in[0];
    const float* init_state   = (const float*)d_in[1];
    // d_in[2], d_in[3]: node_emb0/node_emb1 — unused by the reference
    const float* gate_align_w = (const float*)d_in[4];
    const float* gate_align_b = (const float*)d_in[5];
    const float* gate_w       = (const float*)d_in[6];
    const float* gate_b       = (const float*)d_in[7];
    const float* gate_node_w  = (const float*)d_in[8];
    const float* gate_add_w   = (const float*)d_in[9];
    const float* gate_aff_w   = (const float*)d_in[10];
    const float* gate_aff_b   = (const float*)d_in[11];
    const float* upd_align_w  = (const float*)d_in[12];
    const float* upd_align_b  = (const float*)d_in[13];
    const float* upd_w        = (const float*)d_in[14];
    const float* upd_b        = (const float*)d_in[15];
    const float* upd_node_w   = (const float*)d_in[16];
    const float* upd_add_w    = (const float*)d_in[17];
    const float* upd_aff_w    = (const float*)d_in[18];
    const float* upd_aff_b    = (const float*)d_in[19];
    float* out = (float*)d_out;

    // 66*128*2 + 128*3 + 32*67*2 floats = 86,272 B
    int dyn = (KK * E2 * 2 + E2 * 3 + RT * 67 * 2) * (int)sizeof(float);
    cudaFuncSetAttribute(k_mid, cudaFuncAttributeMaxDynamicSharedMemorySize, dyn);

    dim3 grid(CHUNKS, B);

    k_zero0<<<8, 256>>>();
    k_gate_agg<<<grid, 256>>>(x, init_state, NN * H, gate_w, gate_b, 0, 0);

    for (int t = 0; t < T; t++) {
        const float* state = (t == 0) ? init_state
                                      : (out + (size_t)(t - 1) * NN * H);
        int sstr = (t == 0) ? NN * H : T * NN * H;

        k_mid<<<grid, 256, dyn>>>(x, state, sstr,
                                  gate_align_w, gate_align_b,
                                  upd_w, upd_b, upd_align_w, upd_align_b,
                                  gate_aff_w, gate_aff_b,
                                  gate_node_w, gate_add_w,
                                  t, t & 1, (t + 1) & 1);

        k_final2<<<grid, 256>>>(state, sstr, x, gate_w, gate_b,
                                upd_aff_w, upd_aff_b,
                                upd_node_w, upd_add_w,
                                out, t, t & 1, (t + 1) & 1,
                                (t < T - 1) ? 1 : 0);
    }
}

// round 11
// speedup vs baseline: 1.4497x; 1.2692x over previous
#include <cuda_runtime.h>
#include <math.h>

#define B    16
#define T    12
#define NN   8600
#define H    64
#define E2   128
#define KK   66
#define RPASS 128                                 // rows (nodes) per CTA
#define CHUNKS ((NN + RPASS - 1) / RPASS)         // 68
#define SROW 67                                   // padded row stride (bank-safe)
#define OUT_LAST_OFF ((size_t)B * T * NN * H)

typedef unsigned long long ull;

// ---------------- scratch (device globals; no allocation allowed) --------------
__device__ __align__(16) float g_agg_gate[2][B * E2];
__device__ __align__(16) float g_agg_upd[2][B * H];
__device__ __align__(128) float g_r[(size_t)B * NN * H];     // gate r    (35.2 MB)
__device__ __align__(128) float g_resu[(size_t)B * NN * H];  // res_upd   (35.2 MB)

// ---------------- f32x2 helpers ------------------------------------------------
__device__ __forceinline__ ull pack2(float a) {
    ull r; unsigned int u = __float_as_uint(a);
    asm("mov.b64 %0, {%1, %1};" : "=l"(r) : "r"(u));
    return r;
}
__device__ __forceinline__ void fma2(ull& d, ull a, ull b) {
    asm("fma.rn.f32x2 %0, %1, %2, %3;" : "=l"(d) : "l"(a), "l"(b), "l"(d));
}
__device__ __forceinline__ void unpack2(ull v, float& x, float& y) {
    asm("mov.b64 {%0, %1}, %2;" : "=f"(x), "=f"(y) : "l"(v));
}
__device__ __forceinline__ float sigmoidf_(float x) {
    return 1.0f / (1.0f + __expf(-x));
}

// dot: warp covers 128 rows x 16 cols. lane l -> rows l, l+32, l+64, l+96.
// acc[m][j] accumulates (col e0+2j, e0+2j+1) for row-group m.
__device__ __forceinline__ void dot128(const float* __restrict__ sin_,
                                       const float* __restrict__ sW,
                                       int lane, int e0, ull acc[4][8]) {
    const float* r0 = sin_ + lane * SROW;
    const float* r1 = r0 + 32 * SROW;
    const float* r2 = r1 + 32 * SROW;
    const float* r3 = r2 + 32 * SROW;
    const float* wp = sW + e0;
#pragma unroll 2
    for (int k = 0; k < KK; k++) {
        ull a0 = pack2(r0[k]);
        ull a1 = pack2(r1[k]);
        ull a2 = pack2(r2[k]);
        ull a3 = pack2(r3[k]);
        const ulonglong2* w2 = (const ulonglong2*)(wp + (size_t)k * E2);
        ulonglong2 p0 = w2[0], p1 = w2[1];
        fma2(acc[0][0], a0, p0.x); fma2(acc[0][1], a0, p0.y);
        fma2(acc[1][0], a1, p0.x); fma2(acc[1][1], a1, p0.y);
        fma2(acc[2][0], a2, p0.x); fma2(acc[2][1], a2, p0.y);
        fma2(acc[3][0], a3, p0.x); fma2(acc[3][1], a3, p0.y);
        fma2(acc[0][2], a0, p1.x); fma2(acc[0][3], a0, p1.y);
        fma2(acc[1][2], a1, p1.x); fma2(acc[1][3], a1, p1.y);
        fma2(acc[2][2], a2, p1.x); fma2(acc[2][3], a2, p1.y);
        fma2(acc[3][2], a3, p1.x); fma2(acc[3][3], a3, p1.y);
        ulonglong2 p2 = w2[2], p3 = w2[3];
        fma2(acc[0][4], a0, p2.x); fma2(acc[0][5], a0, p2.y);
        fma2(acc[1][4], a1, p2.x); fma2(acc[1][5], a1, p2.y);
        fma2(acc[2][4], a2, p2.x); fma2(acc[2][5], a2, p2.y);
        fma2(acc[3][4], a3, p2.x); fma2(acc[3][5], a3, p2.y);
        fma2(acc[0][6], a0, p3.x); fma2(acc[0][7], a0, p3.y);
        fma2(acc[1][6], a1, p3.x); fma2(acc[1][7], a1, p3.y);
        fma2(acc[2][6], a2, p3.x); fma2(acc[2][7], a2, p3.y);
        fma2(acc[3][6], a3, p3.x); fma2(acc[3][7], a3, p3.y);
    }
}

// per-warp column reduction + atomic: colsum[16] (each lane holds partial)
__device__ __forceinline__ void colreduce_atomic(float colsum[16], int lane,
                                                 float* dst) {
#pragma unroll
    for (int j = 0; j < 16; j++) {
        float v = colsum[j];
#pragma unroll
        for (int o = 16; o > 0; o >>= 1) v += __shfl_xor_sync(0xffffffffu, v, o);
        colsum[j] = v;
    }
    if (lane == 0) {
#pragma unroll
        for (int j = 0; j < 16; j++) atomicAdd(dst + j, colsum[j]);
    }
}

extern __shared__ float sdyn[];

// =========================== prologue zero =====================================
__global__ void k_zero0() {
    int i = blockIdx.x * blockDim.x + threadIdx.x;
    if (i < B * E2) g_agg_gate[0][i] = 0.0f;
    if (i < B * H)  g_agg_upd[0][i] = 0.0f;
}

// stage [x(2) | state(64)] rows into sin_ (128 rows x SROW)
__device__ __forceinline__ void stage_input(float* sin_, const float* xb,
                                            const float* stb, int base, int tid) {
#pragma unroll
    for (int p = 0; p < 8; p++) {
        int slot = p * 256 + tid;          // 2048 slots = 128 rows x 16 float4
        int row = slot >> 4, q = (slot & 15) * 4;
        int n = base + row;
        float4 v = make_float4(0.f, 0.f, 0.f, 0.f);
        if (n < NN) v = *(const float4*)(stb + (size_t)n * H + q);
        float* d = sin_ + row * SROW + 2 + q;
        d[0] = v.x; d[1] = v.y; d[2] = v.z; d[3] = v.w;
    }
    {
        int row = tid >> 1, kx = tid & 1;
        int n = base + row;
        sin_[row * SROW + kx] = (n < NN) ? xb[(size_t)n * 2 + kx] : 0.0f;
    }
}

// ========== K1 (t=0 only): relu([x,state] @ gate_w + b), agg over nodes ========
__global__ void __launch_bounds__(256, 2) k_gate_agg(
    const float* __restrict__ x, const float* __restrict__ state, int sstr,
    const float* __restrict__ Wg, const float* __restrict__ bg, int t, int pg)
{
    float* sW   = sdyn;              // 66*128
    float* sb   = sW + KK * E2;      // 128
    float* sin_ = sb + E2;           // 128*67

    int tid = threadIdx.x;
    int b = blockIdx.y;
    int base = blockIdx.x * RPASS;

    for (int i = tid; i < KK * E2 / 4; i += 256)
        ((float4*)sW)[i] = ((const float4*)Wg)[i];
    if (tid < E2) sb[tid] = bg[tid];

    const float* xb  = x + (size_t)(b * T + t) * NN * 2;
    const float* stb = state + (size_t)b * sstr;
    stage_input(sin_, xb, stb, base, tid);
    __syncthreads();

    int w = tid >> 5, lane = tid & 31, e0 = w * 16;
    ull acc[4][8];
#pragma unroll
    for (int m = 0; m < 4; m++)
#pragma unroll
        for (int j = 0; j < 8; j++) acc[m][j] = 0ULL;
    dot128(sin_, sW, lane, e0, acc);

    float colsum[16];
#pragma unroll
    for (int j = 0; j < 16; j++) colsum[j] = 0.0f;
#pragma unroll
    for (int m = 0; m < 4; m++) {
        int n = base + lane + 32 * m;
        if (n < NN) {
#pragma unroll
            for (int j = 0; j < 8; j++) {
                float v0, v1; unpack2(acc[m][j], v0, v1);
                colsum[2*j]   += fmaxf(v0 + sb[e0 + 2*j],     0.0f);
                colsum[2*j+1] += fmaxf(v1 + sb[e0 + 2*j + 1], 0.0f);
            }
        }
    }
    colreduce_atomic(colsum, lane, &g_agg_gate[pg][b * E2 + e0]);
}

// ===== K2: sigmoid(zr) via agg_gate; in-place z*state; upd dot; r/resu/agg =====
__global__ void __launch_bounds__(256, 2) k_mid(
    const float* __restrict__ x, const float* __restrict__ state, int sstr,
    const float* __restrict__ Wga, const float* __restrict__ bga,
    const float* __restrict__ Wuw, const float* __restrict__ buw,
    const float* __restrict__ Wua, const float* __restrict__ bua,
    const float* __restrict__ affw, const float* __restrict__ affb,
    const float* __restrict__ nodew, const float* __restrict__ addw,
    int t, int pg, int pn)
{
    float* sWa  = sdyn;               // 66*128 gate_align_w
    float* sWu  = sWa + KK * E2;      // 66*128 [upd_w | upd_align_w]
    float* sba  = sWu + KK * E2;      // 128
    float* sbu  = sba + E2;           // 128
    float* sagg = sbu + E2;           // 128
    float* sin_ = sagg + E2;          // 128*67

    int tid = threadIdx.x;
    int b = blockIdx.y;
    int base = blockIdx.x * RPASS;

    if (blockIdx.x == 0 && blockIdx.y == 0) {     // zero next-parity agg buffers
        for (int i = tid; i < B * E2; i += 256) g_agg_gate[pn][i] = 0.0f;
        for (int i = tid; i < B * H;  i += 256) g_agg_upd[pn][i] = 0.0f;
    }

    for (int i = tid; i < KK * E2 / 4; i += 256)
        ((float4*)sWa)[i] = ((const float4*)Wga)[i];
    for (int i = tid; i < KK * H / 4; i += 256) {
        int k = i / (H / 4), g = i % (H / 4);
        ((float4*)sWu)[k * 32 + g]      = ((const float4*)Wuw)[i];
        ((float4*)sWu)[k * 32 + 16 + g] = ((const float4*)Wua)[i];
    }
    if (tid < E2) {
        sba[tid]  = bga[tid];
        sbu[tid]  = (tid < H) ? buw[tid] : bua[tid - H];
        sagg[tid] = g_agg_gate[pg][b * E2 + tid];
    }

    const float* xb  = x + (size_t)(b * T + t) * NN * 2;
    const float* stb = state + (size_t)b * sstr;
    stage_input(sin_, xb, stb, base, tid);
    __syncthreads();

    int w = tid >> 5, lane = tid & 31, e0 = w * 16;

    // ---- gate-align dot ----
    ull acc[4][8];
#pragma unroll
    for (int m = 0; m < 4; m++)
#pragma unroll
        for (int j = 0; j < 8; j++) acc[m][j] = 0ULL;
    dot128(sin_, sWa, lane, e0, acc);

    // ---- zr epilogue (per lane: 4 rows x 16 cols) ----
    float zr[4][16];
#pragma unroll
    for (int m = 0; m < 4; m++) {
        int n = base + lane + 32 * m;
        if (n < NN) {
            float sgn = addw[n] * nodew[n];
            float aw[16], ab[16];
            const float4* awp = (const float4*)&affw[(size_t)n * E2 + e0];
            const float4* abp = (const float4*)&affb[(size_t)n * E2 + e0];
#pragma unroll
            for (int q = 0; q < 4; q++) {
                ((float4*)aw)[q] = awp[q];
                ((float4*)ab)[q] = abp[q];
            }
#pragma unroll
            for (int j = 0; j < 8; j++) {
                float v0, v1; unpack2(acc[m][j], v0, v1);
                float p0 = v0 + sba[e0 + 2*j]
                         + aw[2*j]   * sgn * sagg[e0 + 2*j]     + ab[2*j];
                float p1 = v1 + sba[e0 + 2*j + 1]
                         + aw[2*j+1] * sgn * sagg[e0 + 2*j + 1] + ab[2*j+1];
                zr[m][2*j]   = sigmoidf_(p0);
                zr[m][2*j+1] = sigmoidf_(p1);
            }
        } else {
#pragma unroll
            for (int j = 0; j < 16; j++) zr[m][j] = 0.0f;
        }
    }

    __syncthreads();                 // all align-dot reads of sin_ complete
    if (w < 4) {                     // z warps: cand = z * state, in place
#pragma unroll
        for (int m = 0; m < 4; m++) {
            float* row = &sin_[(lane + 32 * m) * SROW + 2 + e0];
#pragma unroll
            for (int j = 0; j < 16; j++) row[j] *= zr[m][j];
        }
    } else {                         // r warps: store r
#pragma unroll
        for (int m = 0; m < 4; m++) {
            int n = base + lane + 32 * m;
            if (n < NN) {
                float* rp = &g_r[((size_t)b * NN + n) * H + (e0 - 64)];
#pragma unroll
                for (int q = 0; q < 4; q++)
                    ((float4*)rp)[q] = make_float4(zr[m][4*q], zr[m][4*q+1],
                                                   zr[m][4*q+2], zr[m][4*q+3]);
            }
        }
    }
    __syncthreads();

    // ---- update dot on [x, z*state] ----
#pragma unroll
    for (int m = 0; m < 4; m++)
#pragma unroll
        for (int j = 0; j < 8; j++) acc[m][j] = 0ULL;
    dot128(sin_, sWu, lane, e0, acc);

    if (w < 4) {                     // relu + column aggregate
        float colsum[16];
#pragma unroll
        for (int j = 0; j < 16; j++) colsum[j] = 0.0f;
#pragma unroll
        for (int m = 0; m < 4; m++) {
            int n = base + lane + 32 * m;
            if (n < NN) {
#pragma unroll
                for (int j = 0; j < 8; j++) {
                    float v0, v1; unpack2(acc[m][j], v0, v1);
                    colsum[2*j]   += fmaxf(v0 + sbu[e0 + 2*j],     0.0f);
                    colsum[2*j+1] += fmaxf(v1 + sbu[e0 + 2*j + 1], 0.0f);
                }
            }
        }
        colreduce_atomic(colsum, lane, &g_agg_upd[pg][b * H + e0]);
    } else {                         // res_upd store
#pragma unroll
        for (int m = 0; m < 4; m++) {
            int n = base + lane + 32 * m;
            if (n < NN) {
                float ru[16];
#pragma unroll
                for (int j = 0; j < 8; j++) {
                    float v0, v1; unpack2(acc[m][j], v0, v1);
                    ru[2*j]   = v0 + sbu[e0 + 2*j];
                    ru[2*j+1] = v1 + sbu[e0 + 2*j + 1];
                }
                float* rp = &g_resu[((size_t)b * NN + n) * H + (e0 - 64)];
#pragma unroll
                for (int q = 0; q < 4; q++)
                    ((float4*)rp)[q] = make_float4(ru[4*q], ru[4*q+1],
                                                   ru[4*q+2], ru[4*q+3]);
            }
        }
    }
}

// ===== K3: phase1 = h (coalesced, streams into out + sin_); phase2 = gate dot ==
__global__ void __launch_bounds__(256, 2) k_final2(
    const float* __restrict__ state, int sstr,
    const float* __restrict__ x,
    const float* __restrict__ Wg, const float* __restrict__ bg,
    const float* __restrict__ affw, const float* __restrict__ affb,
    const float* __restrict__ nodew, const float* __restrict__ addw,
    float* __restrict__ out, int t, int pu, int pgn, int do_gate)
{
    float* sW   = sdyn;              // 66*128
    float* sb   = sW + KK * E2;      // 128
    float* sin_ = sb + E2;           // 128*67

    int tid = threadIdx.x;
    int b = blockIdx.y;
    int base = blockIdx.x * RPASS;

    if (do_gate) {
        for (int i = tid; i < KK * E2 / 4; i += 256)
            ((float4*)sW)[i] = ((const float4*)Wg)[i];
        if (tid < E2) sb[tid] = bg[tid];
    }

    const float* stb = state + (size_t)b * sstr;

    // -------- phase 1: h, fully coalesced float4 streams --------
#pragma unroll
    for (int p = 0; p < 8; p++) {
        int slot = p * 256 + tid;            // 2048 slots = 128 rows x 16 float4
        int row = slot >> 4, q = (slot & 15) * 4;
        int n = base + row;
        float4 h4 = make_float4(0.f, 0.f, 0.f, 0.f);
        if (n < NN) {
            size_t ro = ((size_t)b * NN + n) * H + q;
            float4 r4 = *(const float4*)&g_r[ro];
            float4 u4 = *(const float4*)&g_resu[ro];
            float4 s4 = *(const float4*)(stb + (size_t)n * H + q);
            float  su = addw[n] * nodew[n];
            float4 a4 = *(const float4*)(affw + (size_t)n * H + q);
            float4 c4 = *(const float4*)(affb + (size_t)n * H + q);
            float4 g4 = *(const float4*)&g_agg_upd[pu][b * H + q];
            h4.x = r4.x*s4.x + (1.0f-r4.x)*tanhf(u4.x + a4.x*su*g4.x + c4.x);
            h4.y = r4.y*s4.y + (1.0f-r4.y)*tanhf(u4.y + a4.y*su*g4.y + c4.y);
            h4.z = r4.z*s4.z + (1.0f-r4.z)*tanhf(u4.z + a4.z*su*g4.z + c4.z);
            h4.w = r4.w*s4.w + (1.0f-r4.w)*tanhf(u4.w + a4.w*su*g4.w + c4.w);
            *(float4*)(out + ((size_t)(b * T + t) * NN + n) * H + q) = h4;
            if (t == T - 1)
                *(float4*)(out + OUT_LAST_OFF + ((size_t)b * NN + n) * H + q) = h4;
        }
        if (do_gate) {
            float* d = sin_ + row * SROW + 2 + q;
            d[0] = h4.x; d[1] = h4.y; d[2] = h4.z; d[3] = h4.w;
        }
    }
    if (!do_gate) return;
    {
        int row = tid >> 1, kx = tid & 1;
        int n = base + row;
        sin_[row * SROW + kx] = (n < NN)
            ? x[((size_t)(b * T + t + 1) * NN + n) * 2 + kx] : 0.0f;
    }
    __syncthreads();

    // -------- phase 2: gate dot for t+1 + relu aggregate --------
    int w = tid >> 5, lane = tid & 31, e0 = w * 16;
    ull acc[4][8];
#pragma unroll
    for (int m = 0; m < 4; m++)
#pragma unroll
        for (int j = 0; j < 8; j++) acc[m][j] = 0ULL;
    dot128(sin_, sW, lane, e0, acc);

    float colsum[16];
#pragma unroll
    for (int j = 0; j < 16; j++) colsum[j] = 0.0f;
#pragma unroll
    for (int m = 0; m < 4; m++) {
        int n = base + lane + 32 * m;
        if (n < NN) {
#pragma unroll
            for (int j = 0; j < 8; j++) {
                float v0, v1; unpack2(acc[m][j], v0, v1);
                colsum[2*j]   += fmaxf(v0 + sb[e0 + 2*j],     0.0f);
                colsum[2*j+1] += fmaxf(v1 + sb[e0 + 2*j + 1], 0.0f);
            }
        }
    }
    colreduce_atomic(colsum, lane, &g_agg_gate[pgn][b * E2 + e0]);
}

// =============================== launch ========================================
extern "C" void kernel_launch(void* const* d_in, const int* in_sizes, int n_in,
                              void* d_out, int out_size)
{
    const float* x            = (const float*)d_in[0];
    const float* init_state   = (const float*)d_in[1];
    // d_in[2], d_in[3]: node_emb0/node_emb1 — unused by the reference
    const float* gate_align_w = (const float*)d_in[4];
    const float* gate_align_b = (const float*)d_in[5];
    const float* gate_w       = (const float*)d_in[6];
    const float* gate_b       = (const float*)d_in[7];
    const float* gate_node_w  = (const float*)d_in[8];
    const float* gate_add_w   = (const float*)d_in[9];
    const float* gate_aff_w   = (const float*)d_in[10];
    const float* gate_aff_b   = (const float*)d_in[11];
    const float* upd_align_w  = (const float*)d_in[12];
    const float* upd_align_b  = (const float*)d_in[13];
    const float* upd_w        = (const float*)d_in[14];
    const float* upd_b        = (const float*)d_in[15];
    const float* upd_node_w   = (const float*)d_in[16];
    const float* upd_add_w    = (const float*)d_in[17];
    const float* upd_aff_w    = (const float*)d_in[18];
    const float* upd_aff_b    = (const float*)d_in[19];
    float* out = (float*)d_out;

    int dyn_small = (KK * E2 + E2 + RPASS * SROW) * (int)sizeof(float);      // 68,608
    int dyn_mid   = (KK * E2 * 2 + E2 * 3 + RPASS * SROW) * (int)sizeof(float); // 103,424
    cudaFuncSetAttribute(k_gate_agg, cudaFuncAttributeMaxDynamicSharedMemorySize, dyn_small);
    cudaFuncSetAttribute(k_mid,      cudaFuncAttributeMaxDynamicSharedMemorySize, dyn_mid);
    cudaFuncSetAttribute(k_final2,   cudaFuncAttributeMaxDynamicSharedMemorySize, dyn_small);

    dim3 grid(CHUNKS, B);

    k_zero0<<<8, 256>>>();
    k_gate_agg<<<grid, 256, dyn_small>>>(x, init_state, NN * H, gate_w, gate_b, 0, 0);

    for (int t = 0; t < T; t++) {
        const float* state = (t == 0) ? init_state
                                      : (out + (size_t)(t - 1) * NN * H);
        int sstr = (t == 0) ? NN * H : T * NN * H;

        k_mid<<<grid, 256, dyn_mid>>>(x, state, sstr,
                                      gate_align_w, gate_align_b,
                                      upd_w, upd_b, upd_align_w, upd_align_b,
                                      gate_aff_w, gate_aff_b,
                                      gate_node_w, gate_add_w,
                                      t, t & 1, (t + 1) & 1);

        k_final2<<<grid, 256, dyn_small>>>(state, sstr, x, gate_w, gate_b,
                                           upd_aff_w, upd_aff_b,
                                           upd_node_w, upd_add_w,
                                           out, t, t & 1, (t + 1) & 1,
                                           (t < T - 1) ? 1 : 0);
    }
}